// round 1
// baseline (speedup 1.0000x reference)
#include <cuda_runtime.h>
#include <math.h>

#define NN 32768
#define EE 524288
#define CC 16
#define MIDD 32
#define KCC 8
#define HH 8
#define Y0F 0.28209479177387814f
#define CUTOFFF 4.6f
#define KCOULF 0.529f

// ---------------- scratch (device globals; no allocation allowed) ----------------
__device__ __align__(16) float g_x[NN * CC];
__device__ __align__(16) float g_q[NN * HH];
__device__ __align__(16) float g_P[NN * 512];   // [n][o(16)][m(32)]
__device__ __align__(16) float g_PB[NN * CC];   // bias term per (n,o)
__device__ __align__(16) float g_ef[EE * CC];
__device__ __align__(16) float g_val[EE * KCC];
__device__ __align__(16) float g_logits[EE * KCC];
__device__ float g_scale[EE];
__device__ __align__(16) float g_mx[NN * HH];
__device__ __align__(16) float g_denom[NN * HH];
__device__ __align__(16) float g_agg[NN * HH];
__device__ float g_coulN[NN];
__device__ __align__(16) float g_feats[NN * CC];

__device__ __forceinline__ void atomicMaxF(float* addr, float v) {
    if (v >= 0.f) atomicMax((int*)addr, __float_as_int(v));
    else          atomicMin((unsigned int*)addr, __float_as_uint(v));
}

// ---------------- init ----------------
__global__ void k_init_nodes(const int* __restrict__ species,
                             const float* __restrict__ emb,
                             float* __restrict__ out) {
    int n = blockIdx.x * blockDim.x + threadIdx.x;
    if (n >= NN) return;
    int sp = species[n] - 1;
#pragma unroll
    for (int c = 0; c < CC; c++) g_x[n * CC + c] = emb[sp * CC + c];
    g_coulN[n] = 0.f;
    if (n == 0) out[0] = 0.f;
}

__global__ void k_init_edges(const int* __restrict__ src,
                             const int* __restrict__ dst,
                             const float* __restrict__ rel_pos,
                             const int* __restrict__ species) {
    int e = blockIdx.x * blockDim.x + threadIdx.x;
    if (e >= EE) return;
    float px = rel_pos[e * 3 + 0], py = rel_pos[e * 3 + 1], pz = rel_pos[e * 3 + 2];
    float dist = sqrtf(px * px + py * py + pz * pz);
    float xc = dist / CUTOFFF;
    bool in_cut = dist < CUTOFFF;
    float x2 = in_cut ? fminf(xc * xc, 1.f - 1e-6f) : 0.f;
    float scale = in_cut ? expf(3.f - 3.f / (1.f - x2)) : 0.f;
    g_scale[e] = scale;
    // ef init: zeros except last = dist
    float4* efp = (float4*)(g_ef + (size_t)e * CC);
    efp[0] = make_float4(0.f, 0.f, 0.f, 0.f);
    efp[1] = make_float4(0.f, 0.f, 0.f, 0.f);
    efp[2] = make_float4(0.f, 0.f, 0.f, 0.f);
    efp[3] = make_float4(0.f, 0.f, 0.f, dist);
    // coulomb contribution (order-independent of layers)
    float Zu = (float)species[src[e]];
    float Zv = (float)species[dst[e]];
    float raw = KCOULF * Zu * Zv / (2.f * dist);
    float au = 0.8854f * 0.529f / (powf(Zu, 0.23f) + powf(Zv, 0.23f));
    float xx = dist / au;
    float screen = 0.1818f * expf(-3.2f * xx) + 0.5099f * expf(-0.9423f * xx)
                 + 0.2802f * expf(-0.4028f * xx) + 0.02817f * expf(-0.2016f * xx);
    float contrib = raw * screen * scale;
    if (contrib != 0.f) atomicAdd(&g_coulN[dst[e]], contrib);
}

// ---------------- per-layer node precompute: P, PB, q, reset accumulators ----------------
// block = 256 threads = 16 nodes x 16 'o' threads
__global__ void k_node_pre(const float* __restrict__ Wq,
                           const float* __restrict__ W3,
                           const float* __restrict__ b3) {
    __shared__ float sW3[MIDD * 256];   // 32 KB
    __shared__ float sX[16 * CC];
    int tid = threadIdx.x;
    for (int i = tid; i < MIDD * 256; i += 256) sW3[i] = W3[i];
    int n0 = blockIdx.x * 16;
    sX[tid] = g_x[n0 * CC + tid];
    __syncthreads();
    int ln = tid >> 4, o = tid & 15;
    int n = n0 + ln;
    float xr[CC];
#pragma unroll
    for (int i = 0; i < CC; i++) xr[i] = sX[ln * CC + i];

    float* Pn = g_P + (size_t)n * 512 + o * 32;
#pragma unroll 4
    for (int m = 0; m < MIDD; m++) {
        float acc = 0.f;
#pragma unroll
        for (int i = 0; i < CC; i++) acc = fmaf(sW3[m * 256 + o * CC + i], xr[i], acc);
        Pn[m] = acc;
    }
    float accb = 0.f;
#pragma unroll
    for (int i = 0; i < CC; i++) accb = fmaf(b3[o * CC + i], xr[i], accb);
    g_PB[n * CC + o] = accb;

    if (o < HH) {
        float qa = 0.f;
#pragma unroll
        for (int c = 0; c < CC; c++) qa = fmaf(Wq[o * CC + c], xr[c], qa);
        g_q[n * HH + o] = qa;
        g_mx[n * HH + o] = __int_as_float(0xff800000); // -inf
        g_denom[n * HH + o] = 0.f;
        g_agg[n * HH + o] = 0.f;
    }
}

// ---------------- radial MLP (shared weights) ----------------
__device__ __forceinline__ void radial_mlp(const float ef[CC],
                                           const float* sW1, const float* sB1,
                                           const float* sW2, const float* sB2,
                                           float h2[MIDD]) {
    float h1[MIDD];
#pragma unroll
    for (int j = 0; j < MIDD; j++) h1[j] = sB1[j];
#pragma unroll
    for (int i = 0; i < CC; i++) {
        float xi = ef[i];
#pragma unroll
        for (int j = 0; j < MIDD; j++) h1[j] = fmaf(xi, sW1[i * MIDD + j], h1[j]);
    }
#pragma unroll
    for (int j = 0; j < MIDD; j++) h1[j] = fmaxf(h1[j], 0.f);
#pragma unroll
    for (int j = 0; j < MIDD; j++) h2[j] = sB2[j];
#pragma unroll
    for (int i = 0; i < MIDD; i++) {
        float xi = h1[i];
#pragma unroll
        for (int j = 0; j < MIDD; j++) h2[j] = fmaf(xi, sW2[i * MIDD + j], h2[j]);
    }
#pragma unroll
    for (int j = 0; j < MIDD; j++) h2[j] = fmaxf(h2[j], 0.f);
}

// ---------------- edge message: radial MLP + P-contraction + logits + segmax ----------------
__global__ void k_edge_msg(const int* __restrict__ src, const int* __restrict__ dst,
                           const float* __restrict__ W1, const float* __restrict__ b1,
                           const float* __restrict__ W2, const float* __restrict__ b2,
                           int add_prev) {
    __shared__ float sW1[CC * MIDD];
    __shared__ float sW2[MIDD * MIDD];
    __shared__ float sB1[MIDD];
    __shared__ float sB2[MIDD];
    int tid = threadIdx.x;
    for (int i = tid; i < CC * MIDD; i += 256) sW1[i] = W1[i];
    for (int i = tid; i < MIDD * MIDD; i += 256) sW2[i] = W2[i];
    if (tid < MIDD) { sB1[tid] = b1[tid]; sB2[tid] = b2[tid]; }
    __syncthreads();

    int e = blockIdx.x * 256 + tid;
    int s = src[e], d = dst[e];

    float4* efp = (float4*)(g_ef + (size_t)e * CC);
    float4 e0 = efp[0], e1 = efp[1], e2 = efp[2], e3 = efp[3];
    if (add_prev) {
        const float4* xs = (const float4*)(g_x + s * CC);
        float4 x0 = xs[0], x1 = xs[1], x2 = xs[2], x3 = xs[3];
        e0.x += x0.x; e0.y += x0.y; e0.z += x0.z; e0.w += x0.w;
        e1.x += x1.x; e1.y += x1.y; e1.z += x1.z; e1.w += x1.w;
        e2.x += x2.x; e2.y += x2.y; e2.z += x2.z; e2.w += x2.w;
        e3.x += x3.x; e3.y += x3.y; e3.z += x3.z; e3.w += x3.w;
        efp[0] = e0; efp[1] = e1; efp[2] = e2; efp[3] = e3;
    }
    float efv[CC] = {e0.x, e0.y, e0.z, e0.w, e1.x, e1.y, e1.z, e1.w,
                     e2.x, e2.y, e2.z, e2.w, e3.x, e3.y, e3.z, e3.w};
    float h2[MIDD];
    radial_mlp(efv, sW1, sB1, sW2, sB2, h2);

    float bs = Y0F * g_scale[e];
    const float* Pn = g_P + (size_t)s * 512;
    const float* PBn = g_PB + s * CC;
    float kv[CC];
#pragma unroll
    for (int o = 0; o < CC; o++) {
        float acc = PBn[o];
#pragma unroll
        for (int m = 0; m < MIDD; m += 4) {
            float4 p = *(const float4*)(Pn + o * 32 + m);
            acc = fmaf(h2[m], p.x, acc);
            acc = fmaf(h2[m + 1], p.y, acc);
            acc = fmaf(h2[m + 2], p.z, acc);
            acc = fmaf(h2[m + 3], p.w, acc);
        }
        kv[o] = acc * bs;
    }
    // val = kv[0..7], key = kv[8..15]
    float4* vp = (float4*)(g_val + (size_t)e * KCC);
    vp[0] = make_float4(kv[0], kv[1], kv[2], kv[3]);
    vp[1] = make_float4(kv[4], kv[5], kv[6], kv[7]);

    const float4* qp = (const float4*)(g_q + d * HH);
    float4 qa = qp[0], qb = qp[1];
    float lg[HH];
    lg[0] = kv[8] * qa.x;  lg[1] = kv[9] * qa.y;
    lg[2] = kv[10] * qa.z; lg[3] = kv[11] * qa.w;
    lg[4] = kv[12] * qb.x; lg[5] = kv[13] * qb.y;
    lg[6] = kv[14] * qb.z; lg[7] = kv[15] * qb.w;
    float4* lp = (float4*)(g_logits + (size_t)e * KCC);
    lp[0] = make_float4(lg[0], lg[1], lg[2], lg[3]);
    lp[1] = make_float4(lg[4], lg[5], lg[6], lg[7]);
#pragma unroll
    for (int h = 0; h < HH; h++) atomicMaxF(&g_mx[d * HH + h], lg[h]);
}

// ---------------- softmax denominator ----------------
__global__ void k_edge_denom(const int* __restrict__ dst) {
    int e = blockIdx.x * 256 + threadIdx.x;
    float sc = g_scale[e];
    if (sc == 0.f) return;
    int d = dst[e];
    const float4* lp = (const float4*)(g_logits + (size_t)e * KCC);
    float4 l0 = lp[0], l1 = lp[1];
    const float* m = g_mx + d * HH;
#pragma unroll
    for (int h = 0; h < HH; h++) {
        float lg = h < 4 ? (&l0.x)[h] : (&l1.x)[h - 4];
        float w = sc * expf(lg - m[h]);
        atomicAdd(&g_denom[d * HH + h], w);
    }
}

// ---------------- attention aggregation ----------------
__global__ void k_edge_agg(const int* __restrict__ dst) {
    int e = blockIdx.x * 256 + threadIdx.x;
    float sc = g_scale[e];
    if (sc == 0.f) return;
    int d = dst[e];
    const float4* lp = (const float4*)(g_logits + (size_t)e * KCC);
    float4 l0 = lp[0], l1 = lp[1];
    const float4* vp = (const float4*)(g_val + (size_t)e * KCC);
    float4 v0 = vp[0], v1 = vp[1];
    const float* m = g_mx + d * HH;
    const float* dn = g_denom + d * HH;
#pragma unroll
    for (int h = 0; h < HH; h++) {
        float lg = h < 4 ? (&l0.x)[h] : (&l1.x)[h - 4];
        float vv = h < 4 ? (&v0.x)[h] : (&v1.x)[h - 4];
        float attn = sc * expf(lg - m[h]) / fmaxf(dn[h], 1e-20f);
        atomicAdd(&g_agg[d * HH + h], attn * vv);
    }
}

// ---------------- node projection: x = Wproj @ [agg, x] ----------------
__global__ void k_node_post(const float* __restrict__ Wproj) {
    __shared__ float sWp[CC * 24];
    int tid = threadIdx.x;
    for (int i = tid; i < CC * 24; i += 256) sWp[i] = Wproj[i];
    __syncthreads();
    int n = blockIdx.x * 256 + tid;
    float cat[24];
#pragma unroll
    for (int j = 0; j < KCC; j++) cat[j] = g_agg[n * HH + j];
#pragma unroll
    for (int j = 0; j < CC; j++) cat[KCC + j] = g_x[n * CC + j];
    float xn[CC];
#pragma unroll
    for (int c = 0; c < CC; c++) {
        float acc = 0.f;
#pragma unroll
        for (int j = 0; j < 24; j++) acc = fmaf(sWp[c * 24 + j], cat[j], acc);
        xn[c] = acc;
    }
#pragma unroll
    for (int c = 0; c < CC; c++) g_x[n * CC + c] = xn[c];
}

// ---------------- final conv node precompute: P_fin, PB_fin, feats = x @ Wself^T ----------------
__global__ void k_node_pre_fin(const float* __restrict__ W3,
                               const float* __restrict__ b3,
                               const float* __restrict__ Wself) {
    __shared__ float sW3[MIDD * 256];
    __shared__ float sX[16 * CC];
    int tid = threadIdx.x;
    for (int i = tid; i < MIDD * 256; i += 256) sW3[i] = W3[i];
    int n0 = blockIdx.x * 16;
    sX[tid] = g_x[n0 * CC + tid];
    __syncthreads();
    int ln = tid >> 4, o = tid & 15;
    int n = n0 + ln;
    float xr[CC];
#pragma unroll
    for (int i = 0; i < CC; i++) xr[i] = sX[ln * CC + i];

    float* Pn = g_P + (size_t)n * 512 + o * 32;
#pragma unroll 4
    for (int m = 0; m < MIDD; m++) {
        float acc = 0.f;
#pragma unroll
        for (int i = 0; i < CC; i++) acc = fmaf(sW3[m * 256 + o * CC + i], xr[i], acc);
        Pn[m] = acc;
    }
    float accb = 0.f;
#pragma unroll
    for (int i = 0; i < CC; i++) accb = fmaf(b3[o * CC + i], xr[i], accb);
    g_PB[n * CC + o] = accb;

    float fs = 0.f;
#pragma unroll
    for (int j = 0; j < CC; j++) fs = fmaf(Wself[o * CC + j], xr[j], fs);
    g_feats[n * CC + o] = fs;
}

// ---------------- final conv edge pass: feats += segment_sum(m) ----------------
__global__ void k_edge_fin(const int* __restrict__ src, const int* __restrict__ dst,
                           const float* __restrict__ W1, const float* __restrict__ b1,
                           const float* __restrict__ W2, const float* __restrict__ b2) {
    __shared__ float sW1[CC * MIDD];
    __shared__ float sW2[MIDD * MIDD];
    __shared__ float sB1[MIDD];
    __shared__ float sB2[MIDD];
    int tid = threadIdx.x;
    for (int i = tid; i < CC * MIDD; i += 256) sW1[i] = W1[i];
    for (int i = tid; i < MIDD * MIDD; i += 256) sW2[i] = W2[i];
    if (tid < MIDD) { sB1[tid] = b1[tid]; sB2[tid] = b2[tid]; }
    __syncthreads();

    int e = blockIdx.x * 256 + tid;
    float sc = g_scale[e];
    int s = src[e], d = dst[e];

    const float4* efp = (const float4*)(g_ef + (size_t)e * CC);
    const float4* xs = (const float4*)(g_x + s * CC);
    float efv[CC];
#pragma unroll
    for (int k = 0; k < 4; k++) {
        float4 ee = efp[k], xx = xs[k];
        efv[4 * k + 0] = ee.x + xx.x; efv[4 * k + 1] = ee.y + xx.y;
        efv[4 * k + 2] = ee.z + xx.z; efv[4 * k + 3] = ee.w + xx.w;
    }
    float h2[MIDD];
    radial_mlp(efv, sW1, sB1, sW2, sB2, h2);

    float bs = Y0F * sc;
    if (bs == 0.f) return;   // message is zero
    const float* Pn = g_P + (size_t)s * 512;
    const float* PBn = g_PB + s * CC;
#pragma unroll
    for (int o = 0; o < CC; o++) {
        float acc = PBn[o];
#pragma unroll
        for (int m = 0; m < MIDD; m += 4) {
            float4 p = *(const float4*)(Pn + o * 32 + m);
            acc = fmaf(h2[m], p.x, acc);
            acc = fmaf(h2[m + 1], p.y, acc);
            acc = fmaf(h2[m + 2], p.z, acc);
            acc = fmaf(h2[m + 3], p.w, acc);
        }
        atomicAdd(&g_feats[d * CC + o], acc * bs);
    }
}

// ---------------- final per-atom MLP + coulomb + reduce ----------------
__device__ __forceinline__ float siluf(float x) { return x / (1.f + expf(-x)); }

__global__ void k_final(const int* __restrict__ species, const float* __restrict__ emb,
                        const float* __restrict__ W1, const float* __restrict__ b1,
                        const float* __restrict__ W2, const float* __restrict__ b2,
                        const float* __restrict__ W3, const float* __restrict__ b3,
                        float* __restrict__ out) {
    __shared__ float sW1[2 * CC * CC];
    __shared__ float sW2[CC * CC];
    __shared__ float sW3[CC];
    __shared__ float sB1[CC];
    __shared__ float sB2[CC];
    __shared__ float red[256];
    int tid = threadIdx.x;
    for (int i = tid; i < 2 * CC * CC; i += 256) sW1[i] = W1[i];
    for (int i = tid; i < CC * CC; i += 256) sW2[i] = W2[i];
    if (tid < CC) { sW3[tid] = W3[tid]; sB1[tid] = b1[tid]; sB2[tid] = b2[tid]; }
    __syncthreads();

    int n = blockIdx.x * 256 + tid;
    int sp = species[n] - 1;
    float cat[2 * CC];
#pragma unroll
    for (int c = 0; c < CC; c++) cat[c] = emb[sp * CC + c];
#pragma unroll
    for (int c = 0; c < CC; c++) cat[CC + c] = g_feats[n * CC + c];

    float h[CC];
#pragma unroll
    for (int j = 0; j < CC; j++) h[j] = sB1[j];
#pragma unroll
    for (int i = 0; i < 2 * CC; i++) {
        float xi = cat[i];
#pragma unroll
        for (int j = 0; j < CC; j++) h[j] = fmaf(xi, sW1[i * CC + j], h[j]);
    }
#pragma unroll
    for (int j = 0; j < CC; j++) h[j] = siluf(h[j]);

    float h2[CC];
#pragma unroll
    for (int j = 0; j < CC; j++) h2[j] = sB2[j];
#pragma unroll
    for (int i = 0; i < CC; i++) {
        float xi = h[i];
#pragma unroll
        for (int j = 0; j < CC; j++) h2[j] = fmaf(xi, sW2[i * CC + j], h2[j]);
    }
#pragma unroll
    for (int j = 0; j < CC; j++) h2[j] = siluf(h2[j]);

    float learned = b3[0];
#pragma unroll
    for (int i = 0; i < CC; i++) learned = fmaf(h2[i], sW3[i], learned);

    float ae = learned + g_coulN[n];

    red[tid] = ae;
    __syncthreads();
    for (int s = 128; s > 0; s >>= 1) {
        if (tid < s) red[tid] += red[tid + s];
        __syncthreads();
    }
    if (tid == 0) atomicAdd(out, red[0]);
}

// ---------------- host launch ----------------
extern "C" void kernel_launch(void* const* d_in, const int* in_sizes, int n_in,
                              void* d_out, int out_size) {
    const int* species  = (const int*)d_in[0];
    const int* src      = (const int*)d_in[1];
    const int* dst      = (const int*)d_in[2];
    const float* rel_pos = (const float*)d_in[3];
    const float* emb    = (const float*)d_in[4];
    const float* kv_W1  = (const float*)d_in[5];
    const float* kv_b1  = (const float*)d_in[6];
    const float* kv_W2  = (const float*)d_in[7];
    const float* kv_b2  = (const float*)d_in[8];
    const float* kv_W3  = (const float*)d_in[9];
    const float* kv_b3  = (const float*)d_in[10];
    const float* Wq     = (const float*)d_in[11];
    const float* Wproj  = (const float*)d_in[12];
    const float* fin_W1 = (const float*)d_in[13];
    const float* fin_b1 = (const float*)d_in[14];
    const float* fin_W2 = (const float*)d_in[15];
    const float* fin_b2 = (const float*)d_in[16];
    const float* fin_W3 = (const float*)d_in[17];
    const float* fin_b3 = (const float*)d_in[18];
    const float* Wself  = (const float*)d_in[19];
    const float* mlp_W1 = (const float*)d_in[20];
    const float* mlp_b1 = (const float*)d_in[21];
    const float* mlp_W2 = (const float*)d_in[22];
    const float* mlp_b2 = (const float*)d_in[23];
    const float* mlp_W3 = (const float*)d_in[24];
    const float* mlp_b3 = (const float*)d_in[25];
    float* out = (float*)d_out;

    const int EB = EE / 256;   // 2048
    const int NB = NN / 256;   // 128
    const int PB = NN / 16;    // 2048 (node_pre blocks: 16 nodes/block)

    k_init_nodes<<<NB, 256>>>(species, emb, out);
    k_init_edges<<<EB, 256>>>(src, dst, rel_pos, species);

    for (int l = 0; l < 4; l++) {
        k_node_pre<<<PB, 256>>>(Wq + (size_t)l * HH * CC,
                                kv_W3 + (size_t)l * MIDD * 256,
                                kv_b3 + (size_t)l * 256);
        k_edge_msg<<<EB, 256>>>(src, dst,
                                kv_W1 + (size_t)l * CC * MIDD,
                                kv_b1 + (size_t)l * MIDD,
                                kv_W2 + (size_t)l * MIDD * MIDD,
                                kv_b2 + (size_t)l * MIDD,
                                l > 0 ? 1 : 0);
        k_edge_denom<<<EB, 256>>>(dst);
        k_edge_agg<<<EB, 256>>>(dst);
        k_node_post<<<NB, 256>>>(Wproj + (size_t)l * CC * 24);
    }

    k_node_pre_fin<<<PB, 256>>>(fin_W3, fin_b3, Wself);
    k_edge_fin<<<EB, 256>>>(src, dst, fin_W1, fin_b1, fin_W2, fin_b2);
    k_final<<<NB, 256>>>(species, emb, mlp_W1, mlp_b1, mlp_W2, mlp_b2, mlp_W3, mlp_b3, out);
}

// round 2
// speedup vs baseline: 1.7558x; 1.7558x over previous
#include <cuda_runtime.h>
#include <math.h>

#define NN 32768
#define EE 524288
#define CC 16
#define MIDD 32
#define KCC 8
#define HH 8
#define Y0F 0.28209479177387814f
#define CUTOFFF 4.6f
#define KCOULF 0.529f

// ---------------- device scratch ----------------
__device__ __align__(16) float g_x[NN * CC];
__device__ __align__(16) float g_q[NN * HH];
__device__ __align__(16) float g_P[NN * 512];    // [n][mq(8)][o(16)][r(4)]
__device__ __align__(16) float g_PB[NN * CC];
__device__ __align__(16) float g_feats[NN * CC];
__device__ __align__(16) float g_ef[EE * CC];    // src-sorted order
__device__ __align__(16) float g_valD[EE * HH];  // dst-sorted order
__device__ __align__(16) float g_logD[EE * HH];  // dst-sorted order
__device__ __align__(16) float g_msgD[EE * CC];  // dst-sorted order
__device__ float g_scaleS[EE];                   // src-sorted
__device__ float g_scaleD[EE];                   // dst-sorted
__device__ float g_contribD[EE];                 // dst-sorted coulomb contribs
__device__ int g_srcS[EE];
__device__ int g_dstS[EE];
__device__ int g_posd[EE];                       // src-order idx -> dst-order idx
__device__ int g_csrc[NN], g_cdst[NN];
__device__ int g_rdst[NN + 1];
__device__ int g_cursrc[NN], g_curdst[NN];
__device__ int g_rsrc_unused[NN + 1];

// ---------------- init nodes + zero counters ----------------
__global__ void k_init_nodes(const int* __restrict__ species,
                             const float* __restrict__ emb,
                             float* __restrict__ out) {
    int n = blockIdx.x * blockDim.x + threadIdx.x;
    if (n >= NN) return;
    int sp = species[n] - 1;
#pragma unroll
    for (int c = 0; c < CC; c++) g_x[n * CC + c] = emb[sp * CC + c];
    g_csrc[n] = 0;
    g_cdst[n] = 0;
    if (n == 0) out[0] = 0.f;
}

// ---------------- histograms ----------------
__global__ void k_hist(const int* __restrict__ src, const int* __restrict__ dst) {
    int e = blockIdx.x * 256 + threadIdx.x;
    atomicAdd(&g_csrc[src[e]], 1);
    atomicAdd(&g_cdst[dst[e]], 1);
}

// ---------------- exclusive scan (two blocks: 0 = src, 1 = dst) ----------------
__global__ void k_scan() {
    const int T = 1024, PER = NN / 1024; // 32
    __shared__ int part[T];
    int* cnt = blockIdx.x == 0 ? g_csrc : g_cdst;
    int* row = blockIdx.x == 0 ? g_rsrc_unused : g_rdst;
    int* cur = blockIdx.x == 0 ? g_cursrc : g_curdst;
    int t = threadIdx.x;
    int base = t * PER;
    int loc[PER];
    int s = 0;
#pragma unroll
    for (int i = 0; i < PER; i++) { loc[i] = cnt[base + i]; s += loc[i]; }
    part[t] = s;
    __syncthreads();
    for (int off = 1; off < T; off <<= 1) {
        int v = (t >= off) ? part[t - off] : 0;
        __syncthreads();
        part[t] += v;
        __syncthreads();
    }
    int run = part[t] - s; // exclusive
#pragma unroll
    for (int i = 0; i < PER; i++) {
        row[base + i] = run;
        cur[base + i] = run;
        run += loc[i];
    }
    if (t == T - 1) row[NN] = run;
}

// ---------------- scatter into sorted orders + edge geometry ----------------
__global__ void k_scatter(const int* __restrict__ src, const int* __restrict__ dst,
                          const float* __restrict__ rel_pos,
                          const int* __restrict__ species) {
    int e = blockIdx.x * 256 + threadIdx.x;
    int s = src[e], d = dst[e];
    float px = rel_pos[e * 3 + 0], py = rel_pos[e * 3 + 1], pz = rel_pos[e * 3 + 2];
    float dist = sqrtf(px * px + py * py + pz * pz);
    float xc = dist / CUTOFFF;
    bool in_cut = dist < CUTOFFF;
    float x2 = in_cut ? fminf(xc * xc, 1.f - 1e-6f) : 0.f;
    float scale = in_cut ? expf(3.f - 3.f / (1.f - x2)) : 0.f;

    int ps = atomicAdd(&g_cursrc[s], 1);
    int pd = atomicAdd(&g_curdst[d], 1);
    g_srcS[ps] = s;
    g_dstS[ps] = d;
    g_posd[ps] = pd;
    g_scaleS[ps] = scale;
    g_scaleD[pd] = scale;
    float4* efp = (float4*)(g_ef + (size_t)ps * CC);
    efp[0] = make_float4(0.f, 0.f, 0.f, 0.f);
    efp[1] = make_float4(0.f, 0.f, 0.f, 0.f);
    efp[2] = make_float4(0.f, 0.f, 0.f, 0.f);
    efp[3] = make_float4(0.f, 0.f, 0.f, dist);

    float Zu = (float)species[s];
    float Zv = (float)species[d];
    float raw = KCOULF * Zu * Zv / (2.f * dist);
    float au = 0.8854f * 0.529f / (powf(Zu, 0.23f) + powf(Zv, 0.23f));
    float xx = dist / au;
    float screen = 0.1818f * expf(-3.2f * xx) + 0.5099f * expf(-0.9423f * xx)
                 + 0.2802f * expf(-0.4028f * xx) + 0.02817f * expf(-0.2016f * xx);
    g_contribD[pd] = raw * screen * scale;
}

// ---------------- per-layer node precompute: P (chunk layout), PB, q ----------------
__global__ void k_node_pre(const float* __restrict__ Wq,
                           const float* __restrict__ W3,
                           const float* __restrict__ b3) {
    __shared__ float sW3[MIDD * 256]; // 32 KB
    __shared__ float sX[16 * CC];
    int tid = threadIdx.x;
    for (int i = tid; i < MIDD * 256; i += 256) sW3[i] = W3[i];
    int n0 = blockIdx.x * 16;
    sX[tid] = g_x[n0 * CC + tid];
    __syncthreads();
    int ln = tid >> 4, o = tid & 15;
    int n = n0 + ln;
    float xr[CC];
#pragma unroll
    for (int i = 0; i < CC; i++) xr[i] = sX[ln * CC + i];

    float* Pn = g_P + (size_t)n * 512;
#pragma unroll 4
    for (int m = 0; m < MIDD; m++) {
        float acc = 0.f;
#pragma unroll
        for (int i = 0; i < CC; i++) acc = fmaf(sW3[m * 256 + o * CC + i], xr[i], acc);
        Pn[(m >> 2) * 64 + o * 4 + (m & 3)] = acc;
    }
    float accb = 0.f;
#pragma unroll
    for (int i = 0; i < CC; i++) accb = fmaf(b3[o * CC + i], xr[i], accb);
    g_PB[n * CC + o] = accb;

    if (o < HH) {
        float qa = 0.f;
#pragma unroll
        for (int c = 0; c < CC; c++) qa = fmaf(Wq[o * CC + c], xr[c], qa);
        g_q[n * HH + o] = qa;
    }
}

// ---------------- radial MLP ----------------
__device__ __forceinline__ void radial_mlp(const float ef[CC],
                                           const float* sW1, const float* sB1,
                                           const float* sW2, const float* sB2,
                                           float h2[MIDD]) {
    float h1[MIDD];
#pragma unroll
    for (int j = 0; j < MIDD; j++) h1[j] = sB1[j];
#pragma unroll
    for (int i = 0; i < CC; i++) {
        float xi = ef[i];
#pragma unroll
        for (int j = 0; j < MIDD; j++) h1[j] = fmaf(xi, sW1[i * MIDD + j], h1[j]);
    }
#pragma unroll
    for (int j = 0; j < MIDD; j++) h1[j] = fmaxf(h1[j], 0.f);
#pragma unroll
    for (int j = 0; j < MIDD; j++) h2[j] = sB2[j];
#pragma unroll
    for (int i = 0; i < MIDD; i++) {
        float xi = h1[i];
#pragma unroll
        for (int j = 0; j < MIDD; j++) h2[j] = fmaf(xi, sW2[i * MIDD + j], h2[j]);
    }
#pragma unroll
    for (int j = 0; j < MIDD; j++) h2[j] = fmaxf(h2[j], 0.f);
}

// ---------------- edge message (src-sorted) -> val/logits at dst-sorted slots ----------------
__global__ void __launch_bounds__(256, 2)
k_edge_msg(const float* __restrict__ W1, const float* __restrict__ b1,
           const float* __restrict__ W2, const float* __restrict__ b2,
           int add_prev) {
    __shared__ float sW1[CC * MIDD];
    __shared__ float sW2[MIDD * MIDD];
    __shared__ float sB1[MIDD];
    __shared__ float sB2[MIDD];
    __shared__ float sh_h2[256 * 36]; // 36 KB, padded stride 36 (16B aligned rows)
    __shared__ int sh_s[256];
    __shared__ float sh_bs[256];
    __shared__ int sh_pd[256];
    __shared__ int sh_d[256];
    int tid = threadIdx.x;
    for (int i = tid; i < CC * MIDD; i += 256) sW1[i] = W1[i];
    for (int i = tid; i < MIDD * MIDD; i += 256) sW2[i] = W2[i];
    if (tid < MIDD) { sB1[tid] = b1[tid]; sB2[tid] = b2[tid]; }
    __syncthreads();

    // ---- phase A: one thread per edge: ef update + radial MLP ----
    int i = blockIdx.x * 256 + tid;
    int s = g_srcS[i];
    float4* efp = (float4*)(g_ef + (size_t)i * CC);
    float4 e0 = efp[0], e1 = efp[1], e2 = efp[2], e3 = efp[3];
    if (add_prev) {
        const float4* xs = (const float4*)(g_x + s * CC);
        float4 x0 = xs[0], x1 = xs[1], x2 = xs[2], x3 = xs[3];
        e0.x += x0.x; e0.y += x0.y; e0.z += x0.z; e0.w += x0.w;
        e1.x += x1.x; e1.y += x1.y; e1.z += x1.z; e1.w += x1.w;
        e2.x += x2.x; e2.y += x2.y; e2.z += x2.z; e2.w += x2.w;
        e3.x += x3.x; e3.y += x3.y; e3.z += x3.z; e3.w += x3.w;
        efp[0] = e0; efp[1] = e1; efp[2] = e2; efp[3] = e3;
    }
    {
        float efv[CC] = {e0.x, e0.y, e0.z, e0.w, e1.x, e1.y, e1.z, e1.w,
                         e2.x, e2.y, e2.z, e2.w, e3.x, e3.y, e3.z, e3.w};
        float h2[MIDD];
        radial_mlp(efv, sW1, sB1, sW2, sB2, h2);
#pragma unroll
        for (int m = 0; m < MIDD; m++) sh_h2[tid * 36 + m] = h2[m];
    }
    sh_s[tid] = s;
    sh_bs[tid] = Y0F * g_scaleS[i];
    sh_pd[tid] = g_posd[i];
    sh_d[tid] = g_dstS[i];
    __syncthreads();

    // ---- phase B: 8 lanes per edge, coalesced P contraction ----
    int j = tid & 7;
#pragma unroll 1
    for (int sub = 0; sub < 8; sub++) {
        int eloc = sub * 32 + (tid >> 3);
        int es = sh_s[eloc];
        const float* Pn = g_P + (size_t)es * 512;
        float a0 = 0.f, a1 = 0.f;
#pragma unroll
        for (int mq = 0; mq < 8; mq++) {
            float4 h  = *(const float4*)&sh_h2[eloc * 36 + mq * 4];
            float4 p0 = *(const float4*)(Pn + mq * 64 + j * 4);
            float4 p1 = *(const float4*)(Pn + mq * 64 + 32 + j * 4);
            a0 = fmaf(h.x, p0.x, a0); a0 = fmaf(h.y, p0.y, a0);
            a0 = fmaf(h.z, p0.z, a0); a0 = fmaf(h.w, p0.w, a0);
            a1 = fmaf(h.x, p1.x, a1); a1 = fmaf(h.y, p1.y, a1);
            a1 = fmaf(h.z, p1.z, a1); a1 = fmaf(h.w, p1.w, a1);
        }
        float bs = sh_bs[eloc];
        int pd = sh_pd[eloc];
        int d  = sh_d[eloc];
        float val = bs * (g_PB[es * CC + j] + a0);
        float key = bs * (g_PB[es * CC + 8 + j] + a1);
        float lg = key * g_q[d * HH + j];
        g_valD[(size_t)pd * HH + j] = val;
        g_logD[(size_t)pd * HH + j] = lg;
    }
}

// ---------------- node attention (per-node softmax, no atomics) + Wproj ----------------
__global__ void k_node_attn(const float* __restrict__ Wproj) {
    __shared__ float sWp[CC * 24];
    __shared__ float sAgg[32 * 8];
    __shared__ float sX[32 * 16];
    int tid = threadIdx.x;
    for (int i = tid; i < CC * 24; i += 256) sWp[i] = Wproj[i];
    int nloc = tid >> 3, j = tid & 7;
    int n = blockIdx.x * 32 + nloc;
    int beg = g_rdst[n], end = g_rdst[n + 1];
    float mx = -INFINITY;
    for (int i = beg; i < end; i++) mx = fmaxf(mx, g_logD[(size_t)i * HH + j]);
    float num = 0.f, den = 0.f;
    for (int i = beg; i < end; i++) {
        float l = g_logD[(size_t)i * HH + j];
        float sc = g_scaleD[i];
        float w = sc * __expf(l - mx);
        den += w;
        num = fmaf(w, g_valD[(size_t)i * HH + j], num);
    }
    sAgg[nloc * 8 + j] = num / fmaxf(den, 1e-20f);
    sX[nloc * 16 + j] = g_x[n * CC + j];
    sX[nloc * 16 + 8 + j] = g_x[n * CC + 8 + j];
    __syncthreads();
    // projection: thread handles outputs o=j and o=j+8
    float acc0 = 0.f, acc1 = 0.f;
#pragma unroll
    for (int k = 0; k < 8; k++) {
        float c = sAgg[nloc * 8 + k];
        acc0 = fmaf(sWp[j * 24 + k], c, acc0);
        acc1 = fmaf(sWp[(j + 8) * 24 + k], c, acc1);
    }
#pragma unroll
    for (int k = 0; k < 16; k++) {
        float c = sX[nloc * 16 + k];
        acc0 = fmaf(sWp[j * 24 + 8 + k], c, acc0);
        acc1 = fmaf(sWp[(j + 8) * 24 + 8 + k], c, acc1);
    }
    g_x[n * CC + j] = acc0;
    g_x[n * CC + 8 + j] = acc1;
}

// ---------------- final conv node precompute ----------------
__global__ void k_node_pre_fin(const float* __restrict__ W3,
                               const float* __restrict__ b3,
                               const float* __restrict__ Wself) {
    __shared__ float sW3[MIDD * 256];
    __shared__ float sX[16 * CC];
    int tid = threadIdx.x;
    for (int i = tid; i < MIDD * 256; i += 256) sW3[i] = W3[i];
    int n0 = blockIdx.x * 16;
    sX[tid] = g_x[n0 * CC + tid];
    __syncthreads();
    int ln = tid >> 4, o = tid & 15;
    int n = n0 + ln;
    float xr[CC];
#pragma unroll
    for (int i = 0; i < CC; i++) xr[i] = sX[ln * CC + i];

    float* Pn = g_P + (size_t)n * 512;
#pragma unroll 4
    for (int m = 0; m < MIDD; m++) {
        float acc = 0.f;
#pragma unroll
        for (int i = 0; i < CC; i++) acc = fmaf(sW3[m * 256 + o * CC + i], xr[i], acc);
        Pn[(m >> 2) * 64 + o * 4 + (m & 3)] = acc;
    }
    float accb = 0.f;
#pragma unroll
    for (int i = 0; i < CC; i++) accb = fmaf(b3[o * CC + i], xr[i], accb);
    g_PB[n * CC + o] = accb;

    float fs = 0.f;
#pragma unroll
    for (int jj = 0; jj < CC; jj++) fs = fmaf(Wself[o * CC + jj], xr[jj], fs);
    g_feats[n * CC + o] = fs;
}

// ---------------- final conv edge pass -> msg at dst-sorted slots ----------------
__global__ void __launch_bounds__(256, 2)
k_edge_fin(const float* __restrict__ W1, const float* __restrict__ b1,
           const float* __restrict__ W2, const float* __restrict__ b2) {
    __shared__ float sW1[CC * MIDD];
    __shared__ float sW2[MIDD * MIDD];
    __shared__ float sB1[MIDD];
    __shared__ float sB2[MIDD];
    __shared__ float sh_h2[256 * 36];
    __shared__ int sh_s[256];
    __shared__ float sh_bs[256];
    __shared__ int sh_pd[256];
    int tid = threadIdx.x;
    for (int i = tid; i < CC * MIDD; i += 256) sW1[i] = W1[i];
    for (int i = tid; i < MIDD * MIDD; i += 256) sW2[i] = W2[i];
    if (tid < MIDD) { sB1[tid] = b1[tid]; sB2[tid] = b2[tid]; }
    __syncthreads();

    int i = blockIdx.x * 256 + tid;
    int s = g_srcS[i];
    {
        const float4* efp = (const float4*)(g_ef + (size_t)i * CC);
        const float4* xs = (const float4*)(g_x + s * CC);
        float efv[CC];
#pragma unroll
        for (int k = 0; k < 4; k++) {
            float4 ee = efp[k], xx = xs[k];
            efv[4 * k + 0] = ee.x + xx.x; efv[4 * k + 1] = ee.y + xx.y;
            efv[4 * k + 2] = ee.z + xx.z; efv[4 * k + 3] = ee.w + xx.w;
        }
        float h2[MIDD];
        radial_mlp(efv, sW1, sB1, sW2, sB2, h2);
#pragma unroll
        for (int m = 0; m < MIDD; m++) sh_h2[tid * 36 + m] = h2[m];
    }
    sh_s[tid] = s;
    sh_bs[tid] = Y0F * g_scaleS[i];
    sh_pd[tid] = g_posd[i];
    __syncthreads();

    int j = tid & 7;
#pragma unroll 1
    for (int sub = 0; sub < 8; sub++) {
        int eloc = sub * 32 + (tid >> 3);
        int es = sh_s[eloc];
        const float* Pn = g_P + (size_t)es * 512;
        float a0 = 0.f, a1 = 0.f;
#pragma unroll
        for (int mq = 0; mq < 8; mq++) {
            float4 h  = *(const float4*)&sh_h2[eloc * 36 + mq * 4];
            float4 p0 = *(const float4*)(Pn + mq * 64 + j * 4);
            float4 p1 = *(const float4*)(Pn + mq * 64 + 32 + j * 4);
            a0 = fmaf(h.x, p0.x, a0); a0 = fmaf(h.y, p0.y, a0);
            a0 = fmaf(h.z, p0.z, a0); a0 = fmaf(h.w, p0.w, a0);
            a1 = fmaf(h.x, p1.x, a1); a1 = fmaf(h.y, p1.y, a1);
            a1 = fmaf(h.z, p1.z, a1); a1 = fmaf(h.w, p1.w, a1);
        }
        float bs = sh_bs[eloc];
        int pd = sh_pd[eloc];
        g_msgD[(size_t)pd * CC + j]     = bs * (g_PB[es * CC + j] + a0);
        g_msgD[(size_t)pd * CC + 8 + j] = bs * (g_PB[es * CC + 8 + j] + a1);
    }
}

// ---------------- final: gather msg + coulomb + per-atom MLP + reduce ----------------
__device__ __forceinline__ float siluf(float x) { return x / (1.f + __expf(-x)); }

__global__ void k_final(const int* __restrict__ species, const float* __restrict__ emb,
                        const float* __restrict__ W1, const float* __restrict__ b1,
                        const float* __restrict__ W2, const float* __restrict__ b2,
                        const float* __restrict__ W3, const float* __restrict__ b3,
                        float* __restrict__ out) {
    __shared__ float sFeat[16 * 17];
    __shared__ float sEmb[16 * 17];
    __shared__ float sH[16 * 17];
    __shared__ float sCoul[16];
    __shared__ float sRed[16];
    int tid = threadIdx.x;
    int nloc = tid >> 4, o = tid & 15;
    int n = blockIdx.x * 16 + nloc;
    int beg = g_rdst[n], end = g_rdst[n + 1];
    float f = g_feats[n * CC + o];
    for (int i = beg; i < end; i++) f += g_msgD[(size_t)i * CC + o];
    sFeat[nloc * 17 + o] = f;
    if (o == 0) {
        float c = 0.f;
        for (int i = beg; i < end; i++) c += g_contribD[i];
        sCoul[nloc] = c;
    }
    int sp = species[n] - 1;
    sEmb[nloc * 17 + o] = emb[sp * CC + o];
    __syncthreads();

    // h1[o] = silu(b1[o] + sum_i cat[i] * W1[i*16+o]), cat = [emb, feat]
    float h1 = b1[o];
#pragma unroll
    for (int k = 0; k < CC; k++) h1 = fmaf(sEmb[nloc * 17 + k], W1[k * CC + o], h1);
#pragma unroll
    for (int k = 0; k < CC; k++) h1 = fmaf(sFeat[nloc * 17 + k], W1[(CC + k) * CC + o], h1);
    sH[nloc * 17 + o] = siluf(h1);
    __syncthreads();

    float h2 = b2[o];
#pragma unroll
    for (int k = 0; k < CC; k++) h2 = fmaf(sH[nloc * 17 + k], W2[k * CC + o], h2);
    h2 = siluf(h2);

    float part = h2 * W3[o];
    // reduce across 16 lanes of this node
#pragma unroll
    for (int off = 8; off > 0; off >>= 1)
        part += __shfl_down_sync(0xffffffffu, part, off, 16);
    if (o == 0) sRed[nloc] = part + b3[0] + sCoul[nloc];
    __syncthreads();
    if (tid == 0) {
        float acc = 0.f;
#pragma unroll
        for (int k = 0; k < 16; k++) acc += sRed[k];
        atomicAdd(out, acc);
    }
}

// ---------------- host launch ----------------
extern "C" void kernel_launch(void* const* d_in, const int* in_sizes, int n_in,
                              void* d_out, int out_size) {
    const int* species  = (const int*)d_in[0];
    const int* src      = (const int*)d_in[1];
    const int* dst      = (const int*)d_in[2];
    const float* rel_pos = (const float*)d_in[3];
    const float* emb    = (const float*)d_in[4];
    const float* kv_W1  = (const float*)d_in[5];
    const float* kv_b1  = (const float*)d_in[6];
    const float* kv_W2  = (const float*)d_in[7];
    const float* kv_b2  = (const float*)d_in[8];
    const float* kv_W3  = (const float*)d_in[9];
    const float* kv_b3  = (const float*)d_in[10];
    const float* Wq     = (const float*)d_in[11];
    const float* Wproj  = (const float*)d_in[12];
    const float* fin_W1 = (const float*)d_in[13];
    const float* fin_b1 = (const float*)d_in[14];
    const float* fin_W2 = (const float*)d_in[15];
    const float* fin_b2 = (const float*)d_in[16];
    const float* fin_W3 = (const float*)d_in[17];
    const float* fin_b3 = (const float*)d_in[18];
    const float* Wself  = (const float*)d_in[19];
    const float* mlp_W1 = (const float*)d_in[20];
    const float* mlp_b1 = (const float*)d_in[21];
    const float* mlp_W2 = (const float*)d_in[22];
    const float* mlp_b2 = (const float*)d_in[23];
    const float* mlp_W3 = (const float*)d_in[24];
    const float* mlp_b3 = (const float*)d_in[25];
    float* out = (float*)d_out;

    const int EB = EE / 256;   // 2048
    const int NB = NN / 256;   // 128
    const int PB = NN / 16;    // 2048

    k_init_nodes<<<NB, 256>>>(species, emb, out);
    k_hist<<<EB, 256>>>(src, dst);
    k_scan<<<2, 1024>>>();
    k_scatter<<<EB, 256>>>(src, dst, rel_pos, species);

    for (int l = 0; l < 4; l++) {
        k_node_pre<<<PB, 256>>>(Wq + (size_t)l * HH * CC,
                                kv_W3 + (size_t)l * MIDD * 256,
                                kv_b3 + (size_t)l * 256);
        k_edge_msg<<<EB, 256>>>(kv_W1 + (size_t)l * CC * MIDD,
                                kv_b1 + (size_t)l * MIDD,
                                kv_W2 + (size_t)l * MIDD * MIDD,
                                kv_b2 + (size_t)l * MIDD,
                                l > 0 ? 1 : 0);
        k_node_attn<<<NN / 32, 256>>>(Wproj + (size_t)l * CC * 24);
    }

    k_node_pre_fin<<<PB, 256>>>(fin_W3, fin_b3, Wself);
    k_edge_fin<<<EB, 256>>>(fin_W1, fin_b1, fin_W2, fin_b2);
    k_final<<<NN / 16, 256>>>(species, emb, mlp_W1, mlp_b1, mlp_W2, mlp_b2,
                              mlp_W3, mlp_b3, out);
}

// round 3
// speedup vs baseline: 2.5748x; 1.4665x over previous
#include <cuda_runtime.h>
#include <math.h>

#define NN 32768
#define EE 524288
#define CC 16
#define MIDD 32
#define HH 8
#define Y0F 0.28209479177387814f
#define CUTOFFF 4.6f
#define KCOULF 0.529f

// ---------------- device scratch ----------------
__device__ __align__(16) float g_x[NN * CC];
__device__ __align__(16) float g_S[NN * CC];     // running sum of x (for ef)
__device__ __align__(16) float g_q[NN * HH];
__device__ __align__(16) float g_u[NN * MIDD];   // per-node radial layer-1 preact (S@W1 + b1)
__device__ __align__(16) float g_P[NN * 512];    // [n][mq(8)][o(16)][r(4)]
__device__ __align__(16) float g_PB[NN * CC];
__device__ __align__(16) float g_feats[NN * CC];
__device__ __align__(16) float g_valD[EE * HH];  // dst-sorted
__device__ __align__(16) float g_logD[EE * HH];  // dst-sorted
__device__ __align__(16) float g_msgD[EE * CC];  // dst-sorted
__device__ float g_distS[EE];                    // src-sorted
__device__ float g_scaleS[EE];                   // src-sorted
__device__ float g_scaleD[EE];                   // dst-sorted
__device__ float g_contribD[EE];                 // dst-sorted coulomb
__device__ int g_srcS[EE];
__device__ int g_dstS[EE];
__device__ int g_posd[EE];
__device__ int g_csrc[NN], g_cdst[NN];
__device__ int g_rdst[NN + 1];
__device__ int g_cursrc[NN], g_curdst[NN];
__device__ int g_rsrc_unused[NN + 1];

// ---------------- f32x2 helpers ----------------
__device__ __forceinline__ unsigned long long pack2(float a, float b) {
    unsigned long long r;
    asm("mov.b64 %0, {%1, %2};" : "=l"(r) : "f"(a), "f"(b));
    return r;
}
__device__ __forceinline__ unsigned long long fma2(unsigned long long a,
                                                   unsigned long long b,
                                                   unsigned long long c) {
    unsigned long long d;
    asm("fma.rn.f32x2 %0, %1, %2, %3;" : "=l"(d) : "l"(a), "l"(b), "l"(c));
    return d;
}
__device__ __forceinline__ void unpack2(unsigned long long v, float& lo, float& hi) {
    asm("mov.b64 {%0, %1}, %2;" : "=f"(lo), "=f"(hi) : "l"(v));
}

// ---------------- init ----------------
__global__ void k_init_nodes(const int* __restrict__ species,
                             const float* __restrict__ emb,
                             float* __restrict__ out) {
    int n = blockIdx.x * blockDim.x + threadIdx.x;
    if (n >= NN) return;
    int sp = species[n] - 1;
#pragma unroll
    for (int c = 0; c < CC; c++) {
        g_x[n * CC + c] = emb[sp * CC + c];
        g_S[n * CC + c] = 0.f;
    }
    g_csrc[n] = 0;
    g_cdst[n] = 0;
    if (n == 0) out[0] = 0.f;
}

__global__ void k_hist(const int* __restrict__ src, const int* __restrict__ dst) {
    int e = blockIdx.x * 256 + threadIdx.x;
    atomicAdd(&g_csrc[src[e]], 1);
    atomicAdd(&g_cdst[dst[e]], 1);
}

__global__ void k_scan() {
    const int T = 1024, PER = NN / 1024;
    __shared__ int part[T];
    int* cnt = blockIdx.x == 0 ? g_csrc : g_cdst;
    int* row = blockIdx.x == 0 ? g_rsrc_unused : g_rdst;
    int* cur = blockIdx.x == 0 ? g_cursrc : g_curdst;
    int t = threadIdx.x;
    int base = t * PER;
    int loc[PER];
    int s = 0;
#pragma unroll
    for (int i = 0; i < PER; i++) { loc[i] = cnt[base + i]; s += loc[i]; }
    part[t] = s;
    __syncthreads();
    for (int off = 1; off < T; off <<= 1) {
        int v = (t >= off) ? part[t - off] : 0;
        __syncthreads();
        part[t] += v;
        __syncthreads();
    }
    int run = part[t] - s;
#pragma unroll
    for (int i = 0; i < PER; i++) {
        row[base + i] = run;
        cur[base + i] = run;
        run += loc[i];
    }
    if (t == T - 1) row[NN] = run;
}

__global__ void k_scatter(const int* __restrict__ src, const int* __restrict__ dst,
                          const float* __restrict__ rel_pos,
                          const int* __restrict__ species) {
    int e = blockIdx.x * 256 + threadIdx.x;
    int s = src[e], d = dst[e];
    float px = rel_pos[e * 3 + 0], py = rel_pos[e * 3 + 1], pz = rel_pos[e * 3 + 2];
    float dist = sqrtf(px * px + py * py + pz * pz);
    float xc = dist / CUTOFFF;
    bool in_cut = dist < CUTOFFF;
    float x2 = in_cut ? fminf(xc * xc, 1.f - 1e-6f) : 0.f;
    float scale = in_cut ? expf(3.f - 3.f / (1.f - x2)) : 0.f;

    int ps = atomicAdd(&g_cursrc[s], 1);
    int pd = atomicAdd(&g_curdst[d], 1);
    g_srcS[ps] = s;
    g_dstS[ps] = d;
    g_posd[ps] = pd;
    g_distS[ps] = dist;
    g_scaleS[ps] = scale;
    g_scaleD[pd] = scale;

    float Zu = (float)species[s];
    float Zv = (float)species[d];
    float raw = KCOULF * Zu * Zv / (2.f * dist);
    float au = 0.8854f * 0.529f / (powf(Zu, 0.23f) + powf(Zv, 0.23f));
    float xx = dist / au;
    float screen = 0.1818f * expf(-3.2f * xx) + 0.5099f * expf(-0.9423f * xx)
                 + 0.2802f * expf(-0.4028f * xx) + 0.02817f * expf(-0.2016f * xx);
    g_contribD[pd] = raw * screen * scale;
}

// ---------------- fused node kernel ----------------
// mode 0: no attention (initial prep from x=emb, S=0); prep kv weights for layer 0
// mode 1: attention + Wproj + x/S update; prep kv weights for next layer
// mode 2: attention + Wproj + x/S update; prep fin weights + Wself feats (no q)
// 256 threads = 32 nodes x 8 lanes
__global__ void __launch_bounds__(256)
k_node_layer(int mode,
             const float* __restrict__ Wproj,
             const float* __restrict__ Wq,
             const float* __restrict__ W3,
             const float* __restrict__ b3,
             const float* __restrict__ W1n,
             const float* __restrict__ b1n,
             const float* __restrict__ Wself) {
    __shared__ float sW3t[16 * 516 + 4];   // padded transpose: [o][i][m] at o*516+i*32+m
    __shared__ float sW1[CC * MIDD];
    __shared__ float sWq[HH * CC];
    __shared__ float sWproj[CC * 24];
    __shared__ float sb3[256];
    __shared__ float sb1[MIDD];
    __shared__ float sWself[CC * CC];
    __shared__ float sAgg[32 * HH];
    __shared__ float sXold[32 * CC];
    __shared__ float sXn[32 * CC];
    __shared__ float sSn[32 * CC];

    int tid = threadIdx.x;
    int nloc = tid >> 3, j = tid & 7;
    int n = blockIdx.x * 32 + nloc;

    // weight loads
    for (int idx = tid; idx < MIDD * 256; idx += 256) {
        int m = idx >> 8, k = idx & 255;
        int o = k >> 4, i = k & 15;
        sW3t[o * 516 + i * 32 + m] = W3[idx];
    }
    for (int idx = tid; idx < CC * MIDD; idx += 256) sW1[idx] = W1n[idx];
    if (tid < HH * CC && Wq) sWq[tid] = Wq[tid];
    if (mode != 0) for (int idx = tid; idx < CC * 24; idx += 256) sWproj[idx] = Wproj[idx];
    if (tid < 256) sb3[tid] = b3[tid];
    if (tid < MIDD) sb1[tid] = b1n[tid];
    if (tid < CC * CC && Wself) sWself[tid] = Wself[tid];

    if (mode != 0) {
        // attention: lane j = head j of node n
        int beg = g_rdst[n], end = g_rdst[n + 1];
        float mx = -INFINITY;
        for (int i = beg; i < end; i++) mx = fmaxf(mx, g_logD[(size_t)i * HH + j]);
        float num = 0.f, den = 0.f;
        for (int i = beg; i < end; i++) {
            float l = g_logD[(size_t)i * HH + j];
            float w = g_scaleD[i] * __expf(l - mx);
            den += w;
            num = fmaf(w, g_valD[(size_t)i * HH + j], num);
        }
        sAgg[nloc * HH + j] = num / fmaxf(den, 1e-20f);
        sXold[nloc * CC + j] = g_x[n * CC + j];
        sXold[nloc * CC + 8 + j] = g_x[n * CC + 8 + j];
        __syncthreads();
        float xn0 = 0.f, xn1 = 0.f;
#pragma unroll
        for (int k = 0; k < 8; k++) {
            float a = sAgg[nloc * HH + k];
            xn0 = fmaf(sWproj[j * 24 + k], a, xn0);
            xn1 = fmaf(sWproj[(j + 8) * 24 + k], a, xn1);
        }
#pragma unroll
        for (int k = 0; k < CC; k++) {
            float xo = sXold[nloc * CC + k];
            xn0 = fmaf(sWproj[j * 24 + 8 + k], xo, xn0);
            xn1 = fmaf(sWproj[(j + 8) * 24 + 8 + k], xo, xn1);
        }
        float s0 = g_S[n * CC + j] + xn0;
        float s1 = g_S[n * CC + 8 + j] + xn1;
        g_x[n * CC + j] = xn0;     g_x[n * CC + 8 + j] = xn1;
        g_S[n * CC + j] = s0;      g_S[n * CC + 8 + j] = s1;
        sXn[nloc * CC + j] = xn0;  sXn[nloc * CC + 8 + j] = xn1;
        sSn[nloc * CC + j] = s0;   sSn[nloc * CC + 8 + j] = s1;
        __syncthreads();
    } else {
        sXn[nloc * CC + j] = g_x[n * CC + j];
        sXn[nloc * CC + 8 + j] = g_x[n * CC + 8 + j];
        sSn[nloc * CC + j] = 0.f;
        sSn[nloc * CC + 8 + j] = 0.f;
        __syncthreads();
    }

    // q (heads)
    if (mode != 2) {
        float qa = 0.f;
#pragma unroll
        for (int c = 0; c < CC; c++) qa = fmaf(sWq[j * CC + c], sXn[nloc * CC + c], qa);
        g_q[n * HH + j] = qa;
    }
    // u: lane j handles k = j, j+8, j+16, j+24
    {
        float u0 = sb1[j], u1 = sb1[j + 8], u2 = sb1[j + 16], u3 = sb1[j + 24];
#pragma unroll
        for (int c = 0; c < CC; c++) {
            float sv = sSn[nloc * CC + c];
            u0 = fmaf(sv, sW1[c * MIDD + j], u0);
            u1 = fmaf(sv, sW1[c * MIDD + j + 8], u1);
            u2 = fmaf(sv, sW1[c * MIDD + j + 16], u2);
            u3 = fmaf(sv, sW1[c * MIDD + j + 24], u3);
        }
        g_u[n * MIDD + j] = u0;
        g_u[n * MIDD + j + 8] = u1;
        g_u[n * MIDD + j + 16] = u2;
        g_u[n * MIDD + j + 24] = u3;
    }
    // PB: o = j, j+8
    {
        float pb0 = 0.f, pb1 = 0.f;
#pragma unroll
        for (int i = 0; i < CC; i++) {
            float xv = sXn[nloc * CC + i];
            pb0 = fmaf(sb3[j * CC + i], xv, pb0);
            pb1 = fmaf(sb3[(j + 8) * CC + i], xv, pb1);
        }
        g_PB[n * CC + j] = pb0;
        g_PB[n * CC + 8 + j] = pb1;
    }
    // feats self-term (mode 2)
    if (mode == 2) {
        float f0 = 0.f, f1 = 0.f;
#pragma unroll
        for (int i = 0; i < CC; i++) {
            float xv = sXn[nloc * CC + i];
            f0 = fmaf(sWself[j * CC + i], xv, f0);
            f1 = fmaf(sWself[(j + 8) * CC + i], xv, f1);
        }
        g_feats[n * CC + j] = f0;
        g_feats[n * CC + 8 + j] = f1;
    }
    // P: lane j owns o = j and o = j+8; accumulate over i with m-vectorized float4
    {
        float4 acc0[8], acc1[8];
#pragma unroll
        for (int mq = 0; mq < 8; mq++) {
            acc0[mq] = make_float4(0.f, 0.f, 0.f, 0.f);
            acc1[mq] = make_float4(0.f, 0.f, 0.f, 0.f);
        }
#pragma unroll
        for (int i = 0; i < CC; i++) {
            float xv = sXn[nloc * CC + i];
#pragma unroll
            for (int mq = 0; mq < 8; mq++) {
                float4 w0 = *(const float4*)&sW3t[j * 516 + i * 32 + mq * 4];
                float4 w1 = *(const float4*)&sW3t[(j + 8) * 516 + i * 32 + mq * 4];
                acc0[mq].x = fmaf(xv, w0.x, acc0[mq].x);
                acc0[mq].y = fmaf(xv, w0.y, acc0[mq].y);
                acc0[mq].z = fmaf(xv, w0.z, acc0[mq].z);
                acc0[mq].w = fmaf(xv, w0.w, acc0[mq].w);
                acc1[mq].x = fmaf(xv, w1.x, acc1[mq].x);
                acc1[mq].y = fmaf(xv, w1.y, acc1[mq].y);
                acc1[mq].z = fmaf(xv, w1.z, acc1[mq].z);
                acc1[mq].w = fmaf(xv, w1.w, acc1[mq].w);
            }
        }
        float* Pn = g_P + (size_t)n * 512;
#pragma unroll
        for (int mq = 0; mq < 8; mq++) {
            *(float4*)(Pn + mq * 64 + j * 4) = acc0[mq];
            *(float4*)(Pn + mq * 64 + 32 + j * 4) = acc1[mq];
        }
    }
}

// ---------------- edge kernel: u-trick radial + packed W2 + shfl phase B ----------------
template <bool FIN>
__global__ void __launch_bounds__(128)
k_edge(const float* __restrict__ W1, const float* __restrict__ W2,
       const float* __restrict__ b2) {
    __shared__ __align__(16) float sW2[MIDD * MIDD];
    __shared__ __align__(16) float sB2[MIDD];
    __shared__ float sw15[MIDD];
    int tid = threadIdx.x;
    for (int i = tid; i < MIDD * MIDD; i += 128) sW2[i] = W2[i];
    if (tid < MIDD) { sB2[tid] = b2[tid]; sw15[tid] = W1[15 * MIDD + tid]; }
    __syncthreads();

    int e = blockIdx.x * 128 + tid;
    int s = g_srcS[e];
    int dd = g_dstS[e];
    int pd = g_posd[e];
    float dist = g_distS[e];
    float bs = Y0F * g_scaleS[e];

    // h1 = relu(u[src] + dist * w15)
    float h1[MIDD];
    {
        const float4* up = (const float4*)(g_u + (size_t)s * MIDD);
#pragma unroll
        for (int t = 0; t < 8; t++) {
            float4 uv = up[t];
            h1[4 * t + 0] = fmaxf(fmaf(dist, sw15[4 * t + 0], uv.x), 0.f);
            h1[4 * t + 1] = fmaxf(fmaf(dist, sw15[4 * t + 1], uv.y), 0.f);
            h1[4 * t + 2] = fmaxf(fmaf(dist, sw15[4 * t + 2], uv.z), 0.f);
            h1[4 * t + 3] = fmaxf(fmaf(dist, sw15[4 * t + 3], uv.w), 0.f);
        }
    }
    // h2 = relu(W2^T h1 + b2), packed f32x2 over output pairs
    float h2[MIDD];
    {
        unsigned long long acc[16];
#pragma unroll
        for (int jp = 0; jp < 16; jp++)
            acc[jp] = *(const unsigned long long*)&sB2[2 * jp];
#pragma unroll
        for (int i2 = 0; i2 < MIDD; i2++) {
            unsigned long long xx = pack2(h1[i2], h1[i2]);
#pragma unroll
            for (int jp = 0; jp < 16; jp++) {
                unsigned long long w = *(const unsigned long long*)&sW2[i2 * MIDD + 2 * jp];
                acc[jp] = fma2(xx, w, acc[jp]);
            }
        }
#pragma unroll
        for (int jp = 0; jp < 16; jp++) {
            float lo, hi;
            unpack2(acc[jp], lo, hi);
            h2[2 * jp] = fmaxf(lo, 0.f);
            h2[2 * jp + 1] = fmaxf(hi, 0.f);
        }
    }

    // phase B: groups of 8 lanes; broadcast h2 from owner lane b via shfl
    int j = tid & 7;
#pragma unroll 1
    for (int b = 0; b < 8; b++) {
        int es = __shfl_sync(0xffffffffu, s, b, 8);
        int epd = __shfl_sync(0xffffffffu, pd, b, 8);
        float ebs = __shfl_sync(0xffffffffu, bs, b, 8);
        const float* Pn = g_P + (size_t)es * 512;
        float a0 = 0.f, a1 = 0.f;
#pragma unroll
        for (int mq = 0; mq < 8; mq++) {
            float4 p0 = *(const float4*)(Pn + mq * 64 + j * 4);
            float4 p1 = *(const float4*)(Pn + mq * 64 + 32 + j * 4);
            float hx = __shfl_sync(0xffffffffu, h2[mq * 4 + 0], b, 8);
            float hy = __shfl_sync(0xffffffffu, h2[mq * 4 + 1], b, 8);
            float hz = __shfl_sync(0xffffffffu, h2[mq * 4 + 2], b, 8);
            float hw = __shfl_sync(0xffffffffu, h2[mq * 4 + 3], b, 8);
            a0 = fmaf(hx, p0.x, a0); a0 = fmaf(hy, p0.y, a0);
            a0 = fmaf(hz, p0.z, a0); a0 = fmaf(hw, p0.w, a0);
            a1 = fmaf(hx, p1.x, a1); a1 = fmaf(hy, p1.y, a1);
            a1 = fmaf(hz, p1.z, a1); a1 = fmaf(hw, p1.w, a1);
        }
        float v0 = ebs * (g_PB[es * CC + j] + a0);
        float v1 = ebs * (g_PB[es * CC + 8 + j] + a1);
        if (!FIN) {
            int ed = __shfl_sync(0xffffffffu, dd, b, 8);
            float lg = v1 * g_q[ed * HH + j];
            g_valD[(size_t)epd * HH + j] = v0;
            g_logD[(size_t)epd * HH + j] = lg;
        } else {
            g_msgD[(size_t)epd * CC + j] = v0;
            g_msgD[(size_t)epd * CC + 8 + j] = v1;
        }
    }
}

// ---------------- final: gather msg + coulomb + per-atom MLP + reduce ----------------
__device__ __forceinline__ float siluf(float x) { return x / (1.f + __expf(-x)); }

__global__ void k_final(const int* __restrict__ species, const float* __restrict__ emb,
                        const float* __restrict__ W1, const float* __restrict__ b1,
                        const float* __restrict__ W2, const float* __restrict__ b2,
                        const float* __restrict__ W3, const float* __restrict__ b3,
                        float* __restrict__ out) {
    __shared__ float sFeat[16 * 17];
    __shared__ float sEmb[16 * 17];
    __shared__ float sH[16 * 17];
    __shared__ float sCoul[16];
    __shared__ float sRed[16];
    int tid = threadIdx.x;
    int nloc = tid >> 4, o = tid & 15;
    int n = blockIdx.x * 16 + nloc;
    int beg = g_rdst[n], end = g_rdst[n + 1];
    float f = g_feats[n * CC + o];
    for (int i = beg; i < end; i++) f += g_msgD[(size_t)i * CC + o];
    sFeat[nloc * 17 + o] = f;
    if (o == 0) {
        float c = 0.f;
        for (int i = beg; i < end; i++) c += g_contribD[i];
        sCoul[nloc] = c;
    }
    int sp = species[n] - 1;
    sEmb[nloc * 17 + o] = emb[sp * CC + o];
    __syncthreads();

    float h1 = b1[o];
#pragma unroll
    for (int k = 0; k < CC; k++) h1 = fmaf(sEmb[nloc * 17 + k], W1[k * CC + o], h1);
#pragma unroll
    for (int k = 0; k < CC; k++) h1 = fmaf(sFeat[nloc * 17 + k], W1[(CC + k) * CC + o], h1);
    sH[nloc * 17 + o] = siluf(h1);
    __syncthreads();

    float h2 = b2[o];
#pragma unroll
    for (int k = 0; k < CC; k++) h2 = fmaf(sH[nloc * 17 + k], W2[k * CC + o], h2);
    h2 = siluf(h2);

    float part = h2 * W3[o];
#pragma unroll
    for (int off = 8; off > 0; off >>= 1)
        part += __shfl_down_sync(0xffffffffu, part, off, 16);
    if (o == 0) sRed[nloc] = part + b3[0] + sCoul[nloc];
    __syncthreads();
    if (tid == 0) {
        float acc = 0.f;
#pragma unroll
        for (int k = 0; k < 16; k++) acc += sRed[k];
        atomicAdd(out, acc);
    }
}

// ---------------- host launch ----------------
extern "C" void kernel_launch(void* const* d_in, const int* in_sizes, int n_in,
                              void* d_out, int out_size) {
    const int* species  = (const int*)d_in[0];
    const int* src      = (const int*)d_in[1];
    const int* dst      = (const int*)d_in[2];
    const float* rel_pos = (const float*)d_in[3];
    const float* emb    = (const float*)d_in[4];
    const float* kv_W1  = (const float*)d_in[5];
    const float* kv_b1  = (const float*)d_in[6];
    const float* kv_W2  = (const float*)d_in[7];
    const float* kv_b2  = (const float*)d_in[8];
    const float* kv_W3  = (const float*)d_in[9];
    const float* kv_b3  = (const float*)d_in[10];
    const float* Wq     = (const float*)d_in[11];
    const float* Wproj  = (const float*)d_in[12];
    const float* fin_W1 = (const float*)d_in[13];
    const float* fin_b1 = (const float*)d_in[14];
    const float* fin_W2 = (const float*)d_in[15];
    const float* fin_b2 = (const float*)d_in[16];
    const float* fin_W3 = (const float*)d_in[17];
    const float* fin_b3 = (const float*)d_in[18];
    const float* Wself  = (const float*)d_in[19];
    const float* mlp_W1 = (const float*)d_in[20];
    const float* mlp_b1 = (const float*)d_in[21];
    const float* mlp_W2 = (const float*)d_in[22];
    const float* mlp_b2 = (const float*)d_in[23];
    const float* mlp_W3 = (const float*)d_in[24];
    const float* mlp_b3 = (const float*)d_in[25];
    float* out = (float*)d_out;

    const int EB = EE / 256;        // 2048
    const int NB = NN / 256;        // 128
    const int LB = NN / 32;         // 1024 (node_layer blocks)
    const int EB2 = EE / 128;       // 4096 (edge kernel blocks)

    k_init_nodes<<<NB, 256>>>(species, emb, out);
    k_hist<<<EB, 256>>>(src, dst);
    k_scan<<<2, 1024>>>();
    k_scatter<<<EB, 256>>>(src, dst, rel_pos, species);

    // initial prep for layer 0
    k_node_layer<<<LB, 256>>>(0, nullptr,
                              Wq, kv_W3, kv_b3, kv_W1, kv_b1, nullptr);
    for (int l = 0; l < 4; l++) {
        k_edge<false><<<EB2, 128>>>(kv_W1 + (size_t)l * CC * MIDD,
                                    kv_W2 + (size_t)l * MIDD * MIDD,
                                    kv_b2 + (size_t)l * MIDD);
        if (l < 3) {
            k_node_layer<<<LB, 256>>>(1,
                Wproj + (size_t)l * CC * 24,
                Wq + (size_t)(l + 1) * HH * CC,
                kv_W3 + (size_t)(l + 1) * MIDD * 256,
                kv_b3 + (size_t)(l + 1) * 256,
                kv_W1 + (size_t)(l + 1) * CC * MIDD,
                kv_b1 + (size_t)(l + 1) * MIDD,
                nullptr);
        } else {
            k_node_layer<<<LB, 256>>>(2,
                Wproj + (size_t)l * CC * 24,
                nullptr,
                fin_W3, fin_b3, fin_W1, fin_b1, Wself);
        }
    }
    k_edge<true><<<EB2, 128>>>(fin_W1, fin_W2, fin_b2);
    k_final<<<NN / 16, 256>>>(species, emb, mlp_W1, mlp_b1, mlp_W2, mlp_b2,
                              mlp_W3, mlp_b3, out);
}